// round 1
// baseline (speedup 1.0000x reference)
#include <cuda_runtime.h>
#include <math.h>

// ---------------- problem dims ----------------
#define B_    512
#define T_    128
#define IDIM  512
#define N0    538
#define N1    358
#define N2    128
#define K0    (IDIM + N0)   // 1050
#define K1    (N0 + N1)     // 896
#define K2    (N1 + N2)     // 486
#define OUT_  128
#define UNITS 1024

// ---------------- scratch (device globals; no allocs allowed) ----------------
__device__ float g_W0[4 * N0 * K0];   // interleaved stacked weights, layer 0
__device__ float g_W1[4 * N1 * K1];
__device__ float g_W2[4 * N2 * K2];
__device__ float g_bc0[4 * N0];
__device__ float g_bc1[4 * N1];
__device__ float g_bc2[4 * N2];
__device__ float g_h0[2][B_ * N0];
__device__ float g_h1[2][B_ * N1];
__device__ float g_h2[2][B_ * N2];
__device__ float g_motor[B_ * T_ * OUT_];

// ---------------- prep: build masked, interleaved stacked weights ----------------
// Row layout of Wc: row (j*4+g), g in {0:W1*mask, 1:W2*mask, 2:Wa, 3:Wb}
__global__ void build_w(const float* __restrict__ W1, const float* __restrict__ W2,
                        const float* __restrict__ Wa, const float* __restrict__ Wb,
                        const float* __restrict__ mask,
                        const float* __restrict__ b1, const float* __restrict__ b2,
                        const float* __restrict__ ba, const float* __restrict__ bb,
                        float* __restrict__ Wc, float* __restrict__ bc,
                        int n, int K)
{
    int idx = blockIdx.x * blockDim.x + threadIdx.x;
    int tot = 4 * n * K;
    if (idx < tot) {
        int row = idx / K, k = idx - row * K;
        int j = row >> 2, g = row & 3;
        float v;
        if (g == 0)      v = W1[j * K + k] * mask[j * K + k];
        else if (g == 1) v = W2[j * K + k] * mask[j * K + k];
        else if (g == 2) v = Wa[j * K + k];
        else             v = Wb[j * K + k];
        Wc[row * K + k] = v;
    }
    if (idx < 4 * n) {
        int j = idx >> 2, g = idx & 3;
        bc[idx] = (g == 0) ? b1[j] : (g == 1) ? b2[j] : (g == 2) ? ba[j] : bb[j];
    }
}

// ---------------- prep: split h0 (B, 1024) into per-layer buffers ----------------
__global__ void init_h(const float* __restrict__ h0in)
{
    int idx = blockIdx.x * blockDim.x + threadIdx.x;
    if (idx >= B_ * UNITS) return;
    int b = idx / UNITS, c = idx - b * UNITS;
    float v = h0in[idx];
    if (c < N0)           g_h0[0][b * N0 + c] = v;
    else if (c < N0 + N1) g_h1[0][b * N1 + (c - N0)] = v;
    else                  g_h2[0][b * N2 + (c - N0 - N1)] = v;
}

// ---------------- hn = concat(h0, h1, h2) ----------------
__global__ void write_hn(float* __restrict__ out)
{
    int idx = blockIdx.x * blockDim.x + threadIdx.x;
    if (idx >= B_ * UNITS) return;
    int b = idx / UNITS, c = idx - b * UNITS;
    float v;
    if (c < N0)           v = g_h0[0][b * N0 + c];
    else if (c < N0 + N1) v = g_h1[0][b * N1 + (c - N0)];
    else                  v = g_h2[0][b * N2 + (c - N0 - N1)];
    out[idx] = v;
}

// ---------------- fused GEMM + (optional) CfC gate epilogue ----------------
// C[m, :] = act( A[m, :] @ W^T + bias ) where logical A row m is
//   A1[m*lda1 + k]           for k <  k1
//   A2[m*lda2 + (k - k1)]    for k >= k1
// W is row-major (Nout, Ktot).
// GATED: Nout = 4*nUnits with interleaved gate rows; epilogue computes
//   h = ff1 + sig(s)*(ff2 - ff1) and writes h (and optionally to Caux).
#define BM 64
#define BN 64
#define BK 16

template <bool GATED>
__global__ __launch_bounds__(256)
void gemm_cell(const float* __restrict__ A1, int lda1, int k1,
               const float* __restrict__ A2, int lda2, int Ktot,
               const float* __restrict__ W, const float* __restrict__ bias,
               int M, int Nout, int nUnits,
               float* __restrict__ Cmain, int ldcm,
               float* __restrict__ Caux, int ldca)
{
    __shared__ float As[BK][BM + 1];
    __shared__ float Bs[BK][BN + 1];

    int tid = threadIdx.x;
    int tx = tid & 15;        // 0..15 -> column group
    int ty = tid >> 4;        // 0..15 -> row group
    int m0 = blockIdx.y * BM;
    int n0 = blockIdx.x * BN;

    // load assignment: lane kk = tid%16, base index = tid/16, 4 strided passes
    int lK = tid & 15;
    int lI = tid >> 4;

    float acc[4][4] = {};

    for (int kt = 0; kt < Ktot; kt += BK) {
        int k = kt + lK;
        bool kok = (k < Ktot);
        // A tile (coalesced along k per row)
        #pragma unroll
        for (int r = 0; r < 4; r++) {
            int i = lI + 16 * r;
            int grow = m0 + i;          // M is a multiple of 64 for all calls
            float v = 0.f;
            if (kok)
                v = (k < k1) ? A1[(long)grow * lda1 + k]
                             : A2[(long)grow * lda2 + (k - k1)];
            As[lK][i] = v;
        }
        // B tile
        #pragma unroll
        for (int r = 0; r < 4; r++) {
            int j = lI + 16 * r;
            int grow = n0 + j;
            float v = 0.f;
            if (kok && grow < Nout) v = W[(long)grow * Ktot + k];
            Bs[lK][j] = v;
        }
        __syncthreads();

        #pragma unroll
        for (int kk = 0; kk < BK; kk++) {
            float a[4], b[4];
            #pragma unroll
            for (int i = 0; i < 4; i++) a[i] = As[kk][ty * 4 + i];
            #pragma unroll
            for (int j = 0; j < 4; j++) b[j] = Bs[kk][tx * 4 + j];
            #pragma unroll
            for (int i = 0; i < 4; i++)
                #pragma unroll
                for (int j = 0; j < 4; j++)
                    acc[i][j] = fmaf(a[i], b[j], acc[i][j]);
        }
        __syncthreads();
    }

    if (GATED) {
        int u = (n0 >> 2) + tx;       // this thread's unit index
        if (u < nUnits) {
            float b0 = bias[4 * u + 0];
            float b1v = bias[4 * u + 1];
            float b2v = bias[4 * u + 2];
            float b3v = bias[4 * u + 3];
            #pragma unroll
            for (int i = 0; i < 4; i++) {
                int row = m0 + ty * 4 + i;
                float ff1 = tanhf(acc[i][0] + b0);
                float ff2 = tanhf(acc[i][1] + b1v);
                float s   = (acc[i][2] + b2v) + (acc[i][3] + b3v);
                float tg  = 1.f / (1.f + __expf(-s));
                float h   = ff1 + tg * (ff2 - ff1);
                Cmain[(long)row * ldcm + u] = h;
                if (Caux) Caux[(long)row * ldca + u] = h;
            }
        }
    } else {
        #pragma unroll
        for (int i = 0; i < 4; i++) {
            int row = m0 + ty * 4 + i;
            #pragma unroll
            for (int j = 0; j < 4; j++) {
                int col = n0 + tx * 4 + j;
                if (col < Nout)
                    Cmain[(long)row * ldcm + col] = acc[i][j] + bias[col];
            }
        }
    }
}

// ---------------- launcher ----------------
extern "C" void kernel_launch(void* const* d_in, const int* in_sizes, int n_in,
                              void* d_out, int out_size)
{
    (void)in_sizes; (void)n_in;
    const float* x    = (const float*)d_in[0];   // (B, T, IDIM)
    const float* h0in = (const float*)d_in[1];   // (B, 1024)
    // per-layer params
    const float* mask[3]  = { (const float*)d_in[2],  (const float*)d_in[11], (const float*)d_in[20] };
    const float* Wff1[3]  = { (const float*)d_in[3],  (const float*)d_in[12], (const float*)d_in[21] };
    const float* Wff2[3]  = { (const float*)d_in[4],  (const float*)d_in[13], (const float*)d_in[22] };
    const float* Wta[3]   = { (const float*)d_in[5],  (const float*)d_in[14], (const float*)d_in[23] };
    const float* Wtb[3]   = { (const float*)d_in[6],  (const float*)d_in[15], (const float*)d_in[24] };
    const float* bff1[3]  = { (const float*)d_in[7],  (const float*)d_in[16], (const float*)d_in[25] };
    const float* bff2[3]  = { (const float*)d_in[8],  (const float*)d_in[17], (const float*)d_in[26] };
    const float* bta[3]   = { (const float*)d_in[9],  (const float*)d_in[18], (const float*)d_in[27] };
    const float* btb[3]   = { (const float*)d_in[10], (const float*)d_in[19], (const float*)d_in[28] };
    const float* Wfc = (const float*)d_in[29];
    const float* bfc = (const float*)d_in[30];

    float* out = (float*)d_out;
    float* pred = out;                          // (B, T, OUT)
    float* hn   = out + (long)B_ * T_ * OUT_;   // (B, 1024)
    (void)out_size;

    // device global pointers (host-side symbols resolve directly in same TU)
    float* dW[3];  float* dbc[3];
    cudaGetSymbolAddress((void**)&dW[0], g_W0);
    cudaGetSymbolAddress((void**)&dW[1], g_W1);
    cudaGetSymbolAddress((void**)&dW[2], g_W2);
    cudaGetSymbolAddress((void**)&dbc[0], g_bc0);
    cudaGetSymbolAddress((void**)&dbc[1], g_bc1);
    cudaGetSymbolAddress((void**)&dbc[2], g_bc2);
    float* dh0; float* dh1; float* dh2; float* dmotor;
    cudaGetSymbolAddress((void**)&dh0, g_h0);
    cudaGetSymbolAddress((void**)&dh1, g_h1);
    cudaGetSymbolAddress((void**)&dh2, g_h2);
    cudaGetSymbolAddress((void**)&dmotor, g_motor);

    const int nL[3] = { N0, N1, N2 };
    const int kL[3] = { K0, K1, K2 };

    // 1) build stacked/interleaved masked weights + biases
    for (int l = 0; l < 3; l++) {
        int tot = 4 * nL[l] * kL[l];
        int blocks = (tot + 255) / 256;
        build_w<<<blocks, 256>>>(Wff1[l], Wff2[l], Wta[l], Wtb[l], mask[l],
                                 bff1[l], bff2[l], bta[l], btb[l],
                                 dW[l], dbc[l], nL[l], kL[l]);
    }

    // 2) init hidden state buffers (buffer 0)
    init_h<<<(B_ * UNITS + 255) / 256, 256>>>(h0in);

    // 3) recurrence over T steps
    for (int t = 0; t < T_; t++) {
        int p = t & 1;           // read buffer
        int q = 1 - p;           // write buffer
        // layer 0: A = [x_t | h0]
        {
            dim3 grid((4 * N0 + BN - 1) / BN, B_ / BM);
            gemm_cell<true><<<grid, 256>>>(
                x + (long)t * IDIM, T_ * IDIM, IDIM,
                dh0 + (long)p * B_ * N0, N0, K0,
                dW[0], dbc[0], B_, 4 * N0, N0,
                dh0 + (long)q * B_ * N0, N0, nullptr, 0);
        }
        // layer 1: A = [h0_new | h1]
        {
            dim3 grid((4 * N1 + BN - 1) / BN, B_ / BM);
            gemm_cell<true><<<grid, 256>>>(
                dh0 + (long)q * B_ * N0, N0, N0,
                dh1 + (long)p * B_ * N1, N1, K1,
                dW[1], dbc[1], B_, 4 * N1, N1,
                dh1 + (long)q * B_ * N1, N1, nullptr, 0);
        }
        // layer 2: A = [h1_new | h2]; also stream motor output for this t
        {
            dim3 grid((4 * N2 + BN - 1) / BN, B_ / BM);
            gemm_cell<true><<<grid, 256>>>(
                dh1 + (long)q * B_ * N1, N1, N1,
                dh2 + (long)p * B_ * N2, N2, K2,
                dW[2], dbc[2], B_, 4 * N2, N2,
                dh2 + (long)q * B_ * N2, N2,
                dmotor + (long)t * OUT_, T_ * OUT_);
        }
    }

    // 4) predictions = motor @ Wfc^T + bfc   (M = B*T, K = N = 128)
    {
        dim3 grid((OUT_ + BN - 1) / BN, (B_ * T_) / BM);
        gemm_cell<false><<<grid, 256>>>(
            dmotor, OUT_, OUT_,
            dmotor, OUT_, OUT_,   // A2 unused (k1 == Ktot)
            Wfc, bfc, B_ * T_, OUT_, 0,
            pred, OUT_, nullptr, 0);
    }

    // 5) hn = concat(h0, h1, h2), final state lives in buffer 0 (T even)
    write_hn<<<(B_ * UNITS + 255) / 256, 256>>>(hn);
}

// round 2
// speedup vs baseline: 2.7194x; 2.7194x over previous
#include <cuda_runtime.h>
#include <math.h>

// ---------------- problem dims ----------------
#define B_    512
#define T_    128
#define IDIM  512
#define N0    538
#define N1    358
#define N2    128
#define K0    (IDIM + N0)   // 1050
#define K1    (N0 + N1)     // 896
#define K2    (N1 + N2)     // 486
#define OUT_  128
#define UNITS 1024

// ---------------- scratch (device globals; no allocs allowed) ----------------
__device__ float g_W0[4 * N0 * K0];
__device__ float g_W1[4 * N1 * K1];
__device__ float g_W2[4 * N2 * K2];
__device__ float g_bc0[4 * N0];
__device__ float g_bc1[4 * N1];
__device__ float g_bc2[4 * N2];
__device__ float g_h0[2][B_ * N0];
__device__ float g_h1[2][B_ * N1];
__device__ float g_h2[2][B_ * N2];
__device__ float g_motor[B_ * T_ * OUT_];

// ---------------- prep: build masked, interleaved stacked weights ----------------
__global__ void build_w(const float* __restrict__ W1, const float* __restrict__ W2,
                        const float* __restrict__ Wa, const float* __restrict__ Wb,
                        const float* __restrict__ mask,
                        const float* __restrict__ b1, const float* __restrict__ b2,
                        const float* __restrict__ ba, const float* __restrict__ bb,
                        float* __restrict__ Wc, float* __restrict__ bc,
                        int n, int K)
{
    int idx = blockIdx.x * blockDim.x + threadIdx.x;
    int tot = 4 * n * K;
    if (idx < tot) {
        int row = idx / K, k = idx - row * K;
        int j = row >> 2, g = row & 3;
        float v;
        if (g == 0)      v = W1[j * K + k] * mask[j * K + k];
        else if (g == 1) v = W2[j * K + k] * mask[j * K + k];
        else if (g == 2) v = Wa[j * K + k];
        else             v = Wb[j * K + k];
        Wc[row * K + k] = v;
    }
    if (idx < 4 * n) {
        int j = idx >> 2, g = idx & 3;
        bc[idx] = (g == 0) ? b1[j] : (g == 1) ? b2[j] : (g == 2) ? ba[j] : bb[j];
    }
}

__global__ void init_h(const float* __restrict__ h0in)
{
    int idx = blockIdx.x * blockDim.x + threadIdx.x;
    if (idx >= B_ * UNITS) return;
    int b = idx / UNITS, c = idx - b * UNITS;
    float v = h0in[idx];
    if (c < N0)           g_h0[0][b * N0 + c] = v;
    else if (c < N0 + N1) g_h1[0][b * N1 + (c - N0)] = v;
    else                  g_h2[0][b * N2 + (c - N0 - N1)] = v;
}

__global__ void write_hn(float* __restrict__ out)
{
    int idx = blockIdx.x * blockDim.x + threadIdx.x;
    if (idx >= B_ * UNITS) return;
    int b = idx / UNITS, c = idx - b * UNITS;
    float v;
    if (c < N0)           v = g_h0[0][b * N0 + c];
    else if (c < N0 + N1) v = g_h1[0][b * N1 + (c - N0)];
    else                  v = g_h2[0][b * N2 + (c - N0 - N1)];
    out[idx] = v;
}

// ---------------- tf32 tensor-core GEMM + fused CfC gate epilogue ----------------
// C = act( A @ W^T + bias );  A row m: A1[.,k] for k<k1 else A2[.,k-k1]; W row-major (Nout,Ktot)
#define BM 64
#define BN 128
#define BK 32
#define LDK 36                    // BK + 4 pad  -> conflict-free fragment loads
#define LDC 132                   // BN + 4 pad  -> 16B-aligned rows for float4
#define SMEM_BYTES (2*(BM*LDK + BN*LDK)*4)   // 55296 > Cs (BM*LDC*4 = 33792)

__device__ __forceinline__ float f2tf32(float f) {
    unsigned r;
    asm("cvt.rna.tf32.f32 %0, %1;" : "=r"(r) : "f"(f));
    return __uint_as_float(r);
}

__device__ __forceinline__ void mma_tf32(float& c0, float& c1, float& c2, float& c3,
                                         unsigned a0, unsigned a1, unsigned a2, unsigned a3,
                                         unsigned b0, unsigned b1)
{
    asm volatile("mma.sync.aligned.m16n8k8.row.col.f32.tf32.tf32.f32 "
                 "{%0,%1,%2,%3}, {%4,%5,%6,%7}, {%8,%9}, {%0,%1,%2,%3};"
                 : "+f"(c0), "+f"(c1), "+f"(c2), "+f"(c3)
                 : "r"(a0), "r"(a1), "r"(a2), "r"(a3), "r"(b0), "r"(b1));
}

template <bool GATED>
__global__ __launch_bounds__(256)
void gemm_cell_tc(const float* __restrict__ A1, int lda1, int k1,
                  const float* __restrict__ A2, int lda2, int Ktot,
                  const float* __restrict__ W, const float* __restrict__ bias,
                  int Nout, int nUnits,
                  float* __restrict__ Cmain, int ldcm,
                  float* __restrict__ Caux, int ldca)
{
    extern __shared__ float sm[];
    float* As = sm;                         // [2][BM][LDK]
    float* Bs = sm + 2 * BM * LDK;          // [2][BN][LDK]

    const int tid  = threadIdx.x;
    const int lane = tid & 31;
    const int g    = lane >> 2;             // group id 0..7
    const int tk   = lane & 3;              // thread-in-group 0..3
    const int wid  = tid >> 5;
    const int wm   = wid & 1;               // warp M index (2)
    const int wn   = wid >> 1;              // warp N index (4)
    const int m0   = blockIdx.y * BM;
    const int n0   = blockIdx.x * BN;

    const int lK    = tid & 31;             // load column within BK
    const int rbase = tid >> 5;             // load row base (8 row-groups)

    float acc[2][4][4];
    #pragma unroll
    for (int mt = 0; mt < 2; mt++)
        #pragma unroll
        for (int nt = 0; nt < 4; nt++)
            #pragma unroll
            for (int i = 0; i < 4; i++) acc[mt][nt][i] = 0.f;

    const int nkt = (Ktot + BK - 1) / BK;
    float areg[8], breg[16];

    // ---- global load of tile kt into registers ----
    auto ldg_tile = [&](int kt) {
        int k = kt * BK + lK;
        bool kok = (k < Ktot);
        #pragma unroll
        for (int r = 0; r < 8; r++) {
            int row = m0 + rbase + r * 8;
            float v = 0.f;
            if (kok)
                v = (k < k1) ? A1[(long)row * lda1 + k]
                             : A2[(long)row * lda2 + (k - k1)];
            areg[r] = v;
        }
        #pragma unroll
        for (int r = 0; r < 16; r++) {
            int n = n0 + rbase + r * 8;
            float v = 0.f;
            if (kok && n < Nout) v = W[(long)n * Ktot + k];
            breg[r] = v;
        }
    };
    auto sts_tile = [&](int buf) {
        float* a = As + buf * BM * LDK;
        float* b = Bs + buf * BN * LDK;
        #pragma unroll
        for (int r = 0; r < 8; r++)  a[(rbase + r * 8) * LDK + lK] = f2tf32(areg[r]);
        #pragma unroll
        for (int r = 0; r < 16; r++) b[(rbase + r * 8) * LDK + lK] = f2tf32(breg[r]);
    };

    ldg_tile(0);
    sts_tile(0);
    __syncthreads();

    for (int kt = 0; kt < nkt; kt++) {
        if (kt + 1 < nkt) ldg_tile(kt + 1);

        const float* a = As + (kt & 1) * BM * LDK;
        const float* b = Bs + (kt & 1) * BN * LDK;
        #pragma unroll
        for (int ks = 0; ks < BK; ks += 8) {
            unsigned af[2][4], bf[4][2];
            #pragma unroll
            for (int mt = 0; mt < 2; mt++) {
                int row = wm * 32 + mt * 16 + g;
                af[mt][0] = __float_as_uint(a[row * LDK + ks + tk]);
                af[mt][1] = __float_as_uint(a[(row + 8) * LDK + ks + tk]);
                af[mt][2] = __float_as_uint(a[row * LDK + ks + tk + 4]);
                af[mt][3] = __float_as_uint(a[(row + 8) * LDK + ks + tk + 4]);
            }
            #pragma unroll
            for (int nt = 0; nt < 4; nt++) {
                int n = wn * 32 + nt * 8 + g;
                bf[nt][0] = __float_as_uint(b[n * LDK + ks + tk]);
                bf[nt][1] = __float_as_uint(b[n * LDK + ks + tk + 4]);
            }
            #pragma unroll
            for (int mt = 0; mt < 2; mt++)
                #pragma unroll
                for (int nt = 0; nt < 4; nt++)
                    mma_tf32(acc[mt][nt][0], acc[mt][nt][1], acc[mt][nt][2], acc[mt][nt][3],
                             af[mt][0], af[mt][1], af[mt][2], af[mt][3],
                             bf[nt][0], bf[nt][1]);
        }

        if (kt + 1 < nkt) {
            sts_tile((kt + 1) & 1);
            __syncthreads();
        }
    }

    // ---- epilogue: stage C in smem (aliases A/B buffers) ----
    __syncthreads();
    float* Cs = sm;  // [BM][LDC]
    #pragma unroll
    for (int mt = 0; mt < 2; mt++) {
        int row = wm * 32 + mt * 16 + g;
        #pragma unroll
        for (int nt = 0; nt < 4; nt++) {
            int col = wn * 32 + nt * 8 + 2 * tk;
            Cs[row * LDC + col]           = acc[mt][nt][0];
            Cs[row * LDC + col + 1]       = acc[mt][nt][1];
            Cs[(row + 8) * LDC + col]     = acc[mt][nt][2];
            Cs[(row + 8) * LDC + col + 1] = acc[mt][nt][3];
        }
    }
    __syncthreads();

    if (GATED) {
        int ul = tid & 31;                 // unit within CTA tile (32 units)
        int u  = (n0 >> 2) + ul;
        if (u < nUnits) {
            float4 bb = *(const float4*)(bias + 4 * u);
            #pragma unroll
            for (int r = 0; r < 8; r++) {
                int row = (tid >> 5) + 8 * r;
                float4 v = *(const float4*)(Cs + row * LDC + 4 * ul);
                float ff1 = tanhf(v.x + bb.x);
                float ff2 = tanhf(v.y + bb.y);
                float s   = (v.z + bb.z) + (v.w + bb.w);
                float tg  = 1.f / (1.f + __expf(-s));
                float h   = ff1 + tg * (ff2 - ff1);
                long grow = m0 + row;
                Cmain[grow * ldcm + u] = h;
                if (Caux) Caux[grow * ldca + u] = h;
            }
        }
    } else {
        int ul = tid & 31;
        int col = n0 + 4 * ul;
        if (col < Nout) {
            float4 bb = *(const float4*)(bias + col);
            #pragma unroll
            for (int r = 0; r < 8; r++) {
                int row = (tid >> 5) + 8 * r;
                float4 v = *(const float4*)(Cs + row * LDC + 4 * ul);
                v.x += bb.x; v.y += bb.y; v.z += bb.z; v.w += bb.w;
                *(float4*)(Cmain + (long)(m0 + row) * ldcm + col) = v;
            }
        }
    }
}

// ---------------- launcher ----------------
extern "C" void kernel_launch(void* const* d_in, const int* in_sizes, int n_in,
                              void* d_out, int out_size)
{
    (void)in_sizes; (void)n_in; (void)out_size;
    const float* x    = (const float*)d_in[0];
    const float* h0in = (const float*)d_in[1];
    const float* mask[3]  = { (const float*)d_in[2],  (const float*)d_in[11], (const float*)d_in[20] };
    const float* Wff1[3]  = { (const float*)d_in[3],  (const float*)d_in[12], (const float*)d_in[21] };
    const float* Wff2[3]  = { (const float*)d_in[4],  (const float*)d_in[13], (const float*)d_in[22] };
    const float* Wta[3]   = { (const float*)d_in[5],  (const float*)d_in[14], (const float*)d_in[23] };
    const float* Wtb[3]   = { (const float*)d_in[6],  (const float*)d_in[15], (const float*)d_in[24] };
    const float* bff1[3]  = { (const float*)d_in[7],  (const float*)d_in[16], (const float*)d_in[25] };
    const float* bff2[3]  = { (const float*)d_in[8],  (const float*)d_in[17], (const float*)d_in[26] };
    const float* bta[3]   = { (const float*)d_in[9],  (const float*)d_in[18], (const float*)d_in[27] };
    const float* btb[3]   = { (const float*)d_in[10], (const float*)d_in[19], (const float*)d_in[28] };
    const float* Wfc = (const float*)d_in[29];
    const float* bfc = (const float*)d_in[30];

    float* out  = (float*)d_out;
    float* pred = out;
    float* hn   = out + (long)B_ * T_ * OUT_;

    float* dW[3]; float* dbc[3];
    cudaGetSymbolAddress((void**)&dW[0], g_W0);
    cudaGetSymbolAddress((void**)&dW[1], g_W1);
    cudaGetSymbolAddress((void**)&dW[2], g_W2);
    cudaGetSymbolAddress((void**)&dbc[0], g_bc0);
    cudaGetSymbolAddress((void**)&dbc[1], g_bc1);
    cudaGetSymbolAddress((void**)&dbc[2], g_bc2);
    float *dh0, *dh1, *dh2, *dmotor;
    cudaGetSymbolAddress((void**)&dh0, g_h0);
    cudaGetSymbolAddress((void**)&dh1, g_h1);
    cudaGetSymbolAddress((void**)&dh2, g_h2);
    cudaGetSymbolAddress((void**)&dmotor, g_motor);

    static bool attr_done = false;
    if (!attr_done) {
        cudaFuncSetAttribute(gemm_cell_tc<true>,  cudaFuncAttributeMaxDynamicSharedMemorySize, SMEM_BYTES);
        cudaFuncSetAttribute(gemm_cell_tc<false>, cudaFuncAttributeMaxDynamicSharedMemorySize, SMEM_BYTES);
        attr_done = true;
    }

    const int nL[3] = { N0, N1, N2 };
    const int kL[3] = { K0, K1, K2 };

    for (int l = 0; l < 3; l++) {
        int tot = 4 * nL[l] * kL[l];
        build_w<<<(tot + 255) / 256, 256>>>(Wff1[l], Wff2[l], Wta[l], Wtb[l], mask[l],
                                            bff1[l], bff2[l], bta[l], btb[l],
                                            dW[l], dbc[l], nL[l], kL[l]);
    }
    init_h<<<(B_ * UNITS + 255) / 256, 256>>>(h0in);

    for (int t = 0; t < T_; t++) {
        int p = t & 1, q = 1 - p;
        {   // layer 0: A = [x_t | h0]
            dim3 grid((4 * N0 + BN - 1) / BN, B_ / BM);
            gemm_cell_tc<true><<<grid, 256, SMEM_BYTES>>>(
                x + (long)t * IDIM, T_ * IDIM, IDIM,
                dh0 + (long)p * B_ * N0, N0, K0,
                dW[0], dbc[0], 4 * N0, N0,
                dh0 + (long)q * B_ * N0, N0, nullptr, 0);
        }
        {   // layer 1: A = [h0_new | h1]
            dim3 grid((4 * N1 + BN - 1) / BN, B_ / BM);
            gemm_cell_tc<true><<<grid, 256, SMEM_BYTES>>>(
                dh0 + (long)q * B_ * N0, N0, N0,
                dh1 + (long)p * B_ * N1, N1, K1,
                dW[1], dbc[1], 4 * N1, N1,
                dh1 + (long)q * B_ * N1, N1, nullptr, 0);
        }
        {   // layer 2: A = [h1_new | h2] + motor stream
            dim3 grid((4 * N2 + BN - 1) / BN, B_ / BM);
            gemm_cell_tc<true><<<grid, 256, SMEM_BYTES>>>(
                dh1 + (long)q * B_ * N1, N1, N1,
                dh2 + (long)p * B_ * N2, N2, K2,
                dW[2], dbc[2], 4 * N2, N2,
                dh2 + (long)q * B_ * N2, N2,
                dmotor + (long)t * OUT_, T_ * OUT_);
        }
    }

    {   // predictions = motor @ Wfc^T + bfc  (M = B*T = 65536, N = K = 128)
        dim3 grid(1, (B_ * T_) / BM);
        gemm_cell_tc<false><<<grid, 256, SMEM_BYTES>>>(
            dmotor, OUT_, OUT_,
            dmotor, OUT_, OUT_,
            Wfc, bfc, OUT_, 0,
            pred, OUT_, nullptr, 0);
    }

    write_hn<<<(B_ * UNITS + 255) / 256, 256>>>(hn);
}

// round 3
// speedup vs baseline: 5.8296x; 2.1437x over previous
#include <cuda_runtime.h>
#include <math.h>

// ---------------- problem dims ----------------
#define B_    512
#define T_    128
#define IDIM  512
#define N0    538
#define N1    358
#define N2    128
#define K0    1050     // IDIM + N0
#define K1    896      // N0 + N1
#define K2    486      // N1 + N2
#define KP0   1056     // K0 padded to 32
#define KP1   896
#define KP2   512
#define OUT_  128
#define UNITS 1024

// tile config
#define BM 128
#define BN 128
#define BK 32
#define LDK 36
#define LDC 132
#define SMEM_FLOATS (4*BM*LDK)       // As[2][128][36] + Bs[2][128][36] = 18432 floats
#define SMEM_BYTES  (SMEM_FLOATS*4)  // 73728 B (Cs staging 128*132=16896 floats fits)

#define NCTA 132                      // 68 (L0) + 48 (L1) + 16 (L2) tiles

// ---------------- scratch (device globals; no allocs allowed) ----------------
__device__ __align__(16) float g_W0[4 * N0 * KP0];
__device__ __align__(16) float g_W1[4 * N1 * KP1];
__device__ __align__(16) float g_W2[4 * N2 * KP2];
__device__ __align__(16) float g_bc0[4 * N0];
__device__ __align__(16) float g_bc1[4 * N1];
__device__ __align__(16) float g_bc2[4 * N2];
__device__ __align__(16) float g_h0[2][B_ * N0];
__device__ __align__(16) float g_h1[2][B_ * N1];
__device__ __align__(16) float g_h2[2][B_ * N2];
__device__ __align__(16) float g_motor[B_ * T_ * OUT_];
__device__ unsigned g_bar_count;
__device__ unsigned g_bar_release;

// ---------------- prep kernels ----------------
__global__ void build_w(const float* __restrict__ W1, const float* __restrict__ W2,
                        const float* __restrict__ Wa, const float* __restrict__ Wb,
                        const float* __restrict__ mask,
                        const float* __restrict__ b1, const float* __restrict__ b2,
                        const float* __restrict__ ba, const float* __restrict__ bb,
                        float* __restrict__ Wc, float* __restrict__ bc,
                        int n, int K, int KP)
{
    int idx = blockIdx.x * blockDim.x + threadIdx.x;
    int tot = 4 * n * KP;
    if (idx < tot) {
        int row = idx / KP, k = idx - row * KP;
        float v = 0.f;
        if (k < K) {
            int j = row >> 2, g = row & 3;
            if (g == 0)      v = W1[j * K + k] * mask[j * K + k];
            else if (g == 1) v = W2[j * K + k] * mask[j * K + k];
            else if (g == 2) v = Wa[j * K + k];
            else             v = Wb[j * K + k];
        }
        Wc[idx] = v;
    }
    if (idx < 4 * n) {
        int j = idx >> 2, g = idx & 3;
        bc[idx] = (g == 0) ? b1[j] : (g == 1) ? b2[j] : (g == 2) ? ba[j] : bb[j];
    }
}

__global__ void init_h(const float* __restrict__ h0in)
{
    int idx = blockIdx.x * blockDim.x + threadIdx.x;
    if (idx >= B_ * UNITS) return;
    int b = idx / UNITS, c = idx - b * UNITS;
    float v = h0in[idx];
    if (c < N0)           g_h0[0][b * N0 + c] = v;
    else if (c < N0 + N1) g_h1[0][b * N1 + (c - N0)] = v;
    else                  g_h2[0][b * N2 + (c - N0 - N1)] = v;
}

__global__ void write_hn(float* __restrict__ out)
{
    int idx = blockIdx.x * blockDim.x + threadIdx.x;
    if (idx >= B_ * UNITS) return;
    int b = idx / UNITS, c = idx - b * UNITS;
    float v;
    if (c < N0)           v = g_h0[0][b * N0 + c];
    else if (c < N0 + N1) v = g_h1[0][b * N1 + (c - N0)];
    else                  v = g_h2[0][b * N2 + (c - N0 - N1)];
    out[idx] = v;
}

__global__ void reset_bar() { g_bar_count = 0; g_bar_release = 0; }

// ---------------- helpers ----------------
__device__ __forceinline__ float f2tf32(float f) {
    unsigned r;
    asm("cvt.rna.tf32.f32 %0, %1;" : "=r"(r) : "f"(f));
    return __uint_as_float(r);
}

__device__ __forceinline__ void mma_tf32(float& c0, float& c1, float& c2, float& c3,
                                         unsigned a0, unsigned a1, unsigned a2, unsigned a3,
                                         unsigned b0, unsigned b1)
{
    asm volatile("mma.sync.aligned.m16n8k8.row.col.f32.tf32.tf32.f32 "
                 "{%0,%1,%2,%3}, {%4,%5,%6,%7}, {%8,%9}, {%0,%1,%2,%3};"
                 : "+f"(c0), "+f"(c1), "+f"(c2), "+f"(c3)
                 : "r"(a0), "r"(a1), "r"(a2), "r"(a3), "r"(b0), "r"(b1));
}

__device__ __forceinline__ void grid_bar(int epoch)
{
    __syncthreads();
    if (threadIdx.x == 0) {
        __threadfence();
        unsigned a = atomicAdd(&g_bar_count, 1u) + 1u;
        if (a == (unsigned)(NCTA * epoch)) {
            asm volatile("st.global.release.gpu.u32 [%0], %1;"
                         :: "l"(&g_bar_release), "r"((unsigned)epoch) : "memory");
        } else {
            unsigned r;
            do {
                asm volatile("ld.global.acquire.gpu.u32 %0, [%1];"
                             : "=r"(r) : "l"(&g_bar_release) : "memory");
            } while (r < (unsigned)epoch);
        }
    }
    __syncthreads();
}

// ---------------- one 128x128 GEMM tile + fused CfC gate ----------------
// C = act( A @ W^T + bias ); logical A row m: A1[m,k] for k<k1 else A2[m,k-k1]
// W row-major (Nout, KP), zero-padded on [Ktot, KP).
template <bool GATED>
__device__ __forceinline__ void cell_tile(
    const float* __restrict__ A1, int lda1, int k1,
    const float* __restrict__ A2, int lda2, int Ktot, int KP,
    const float* __restrict__ W, const float* __restrict__ bias,
    int Nout, int nUnits,
    float* __restrict__ Cmain, int ldcm,
    float* __restrict__ Caux, int ldca,
    int m0, int n0, float* sm)
{
    float* As = sm;                       // [2][BM][LDK]
    float* Bs = sm + 2 * BM * LDK;        // [2][BN][LDK]

    const int tid  = threadIdx.x;
    const int lane = tid & 31;
    const int g    = lane >> 2;
    const int tk   = lane & 3;
    const int wid  = tid >> 5;
    const int wm   = wid & 1;             // 2 warps in M  -> 64 rows each
    const int wn   = wid >> 1;            // 4 warps in N  -> 32 cols each

    const int lK  = tid & 31;             // A load: column in BK
    const int arb = tid >> 5;             // A load: row base (stride 8)
    const int bkg = (tid & 7) * 4;        // B load: k group (float4)
    const int bnb = tid >> 3;             // B load: n base (stride 32)

    float acc[4][4][4];
    #pragma unroll
    for (int mt = 0; mt < 4; mt++)
        #pragma unroll
        for (int nt = 0; nt < 4; nt++)
            #pragma unroll
            for (int i = 0; i < 4; i++) acc[mt][nt][i] = 0.f;

    const int nkt = KP / BK;
    float  areg[16];
    float4 breg[4];

    auto ldg = [&](int kt) {
        int k = kt * BK + lK;
        #pragma unroll
        for (int r = 0; r < 16; r++) {
            int row = m0 + arb + r * 8;
            float v = 0.f;
            if (k < Ktot)
                v = (k < k1) ? A1[(long)row * lda1 + k]
                             : A2[(long)row * lda2 + (k - k1)];
            areg[r] = v;
        }
        int kb = kt * BK + bkg;
        #pragma unroll
        for (int r = 0; r < 4; r++) {
            int n = n0 + bnb + r * 32;
            float4 v = make_float4(0.f, 0.f, 0.f, 0.f);
            if (n < Nout) v = *(const float4*)(W + (long)n * KP + kb);
            breg[r] = v;
        }
    };
    auto sts = [&](int buf) {
        float* a = As + buf * BM * LDK;
        float* b = Bs + buf * BM * LDK;
        #pragma unroll
        for (int r = 0; r < 16; r++) a[(arb + r * 8) * LDK + lK] = f2tf32(areg[r]);
        #pragma unroll
        for (int r = 0; r < 4; r++) {
            float4 v = breg[r];
            v.x = f2tf32(v.x); v.y = f2tf32(v.y); v.z = f2tf32(v.z); v.w = f2tf32(v.w);
            *(float4*)(b + (bnb + r * 32) * LDK + bkg) = v;
        }
    };

    ldg(0);
    sts(0);
    __syncthreads();

    for (int kt = 0; kt < nkt; kt++) {
        if (kt + 1 < nkt) ldg(kt + 1);

        const float* a = As + (kt & 1) * BM * LDK;
        const float* b = Bs + (kt & 1) * BM * LDK;
        #pragma unroll
        for (int ks = 0; ks < BK; ks += 8) {
            unsigned af[4][4], bf[4][2];
            #pragma unroll
            for (int mt = 0; mt < 4; mt++) {
                int row = wm * 64 + mt * 16 + g;
                af[mt][0] = __float_as_uint(a[row * LDK + ks + tk]);
                af[mt][1] = __float_as_uint(a[(row + 8) * LDK + ks + tk]);
                af[mt][2] = __float_as_uint(a[row * LDK + ks + tk + 4]);
                af[mt][3] = __float_as_uint(a[(row + 8) * LDK + ks + tk + 4]);
            }
            #pragma unroll
            for (int nt = 0; nt < 4; nt++) {
                int n = wn * 32 + nt * 8 + g;
                bf[nt][0] = __float_as_uint(b[n * LDK + ks + tk]);
                bf[nt][1] = __float_as_uint(b[n * LDK + ks + tk + 4]);
            }
            #pragma unroll
            for (int mt = 0; mt < 4; mt++)
                #pragma unroll
                for (int nt = 0; nt < 4; nt++)
                    mma_tf32(acc[mt][nt][0], acc[mt][nt][1], acc[mt][nt][2], acc[mt][nt][3],
                             af[mt][0], af[mt][1], af[mt][2], af[mt][3],
                             bf[nt][0], bf[nt][1]);
        }

        if (kt + 1 < nkt) {
            sts((kt + 1) & 1);
            __syncthreads();
        }
    }

    // ---- epilogue: stage C in smem (aliases A/B buffers) ----
    __syncthreads();
    float* Cs = sm;                       // [BM][LDC]
    #pragma unroll
    for (int mt = 0; mt < 4; mt++) {
        int row = wm * 64 + mt * 16 + g;
        #pragma unroll
        for (int nt = 0; nt < 4; nt++) {
            int col = wn * 32 + nt * 8 + 2 * tk;
            Cs[row * LDC + col]           = acc[mt][nt][0];
            Cs[row * LDC + col + 1]       = acc[mt][nt][1];
            Cs[(row + 8) * LDC + col]     = acc[mt][nt][2];
            Cs[(row + 8) * LDC + col + 1] = acc[mt][nt][3];
        }
    }
    __syncthreads();

    if (GATED) {
        int ul = tid & 31;
        int u  = (n0 >> 2) + ul;
        if (u < nUnits) {
            float4 bb = *(const float4*)(bias + 4 * u);
            #pragma unroll
            for (int r = 0; r < 16; r++) {
                int row = (tid >> 5) + 8 * r;
                float4 v = *(const float4*)(Cs + row * LDC + 4 * ul);
                float ff1 = tanhf(v.x + bb.x);
                float ff2 = tanhf(v.y + bb.y);
                float s   = (v.z + bb.z) + (v.w + bb.w);
                float tg  = 1.f / (1.f + __expf(-s));
                float h   = ff1 + tg * (ff2 - ff1);
                long grow = m0 + row;
                Cmain[grow * ldcm + u] = h;
                if (Caux) Caux[grow * ldca + u] = h;
            }
        }
    } else {
        int ul  = tid & 31;
        int col = n0 + 4 * ul;
        if (col < Nout) {
            float4 bb = *(const float4*)(bias + col);
            #pragma unroll
            for (int r = 0; r < 16; r++) {
                int row = (tid >> 5) + 8 * r;
                float4 v = *(const float4*)(Cs + row * LDC + 4 * ul);
                v.x += bb.x; v.y += bb.y; v.z += bb.z; v.w += bb.w;
                *(float4*)(Cmain + (long)(m0 + row) * ldcm + col) = v;
            }
        }
    }
    __syncthreads();   // protect smem before next phase reuses it
}

// ---------------- persistent wavefront kernel ----------------
// phase p: L0 computes step p, L1 step p-1, L2 step p-2; one grid barrier per phase.
__global__ __launch_bounds__(256, 1)
void rnn_persistent(const float* __restrict__ x)
{
    extern __shared__ float sm[];
    const int bid = blockIdx.x;

    for (int p = 0; p < T_ + 2; p++) {
        if (bid < 68) {                       // layer 0: 4 x 17 tiles
            int t = p;
            if (t < T_) {
                int row = bid & 3, col = bid >> 2;
                int rp = t & 1, wp = 1 - rp;
                cell_tile<true>(x + (long)t * IDIM, T_ * IDIM, IDIM,
                                g_h0[rp], N0, K0, KP0,
                                g_W0, g_bc0, 4 * N0, N0,
                                g_h0[wp], N0, nullptr, 0,
                                row * BM, col * BN, sm);
            }
        } else if (bid < 116) {               // layer 1: 4 x 12 tiles
            int t = p - 1;
            if (t >= 0 && t < T_) {
                int b = bid - 68;
                int row = b & 3, col = b >> 2;
                int rp = t & 1, wp = 1 - rp;
                cell_tile<true>(g_h0[wp], N0, N0,      // h0 after step t lives in buffer wp
                                g_h1[rp], N1, K1, KP1,
                                g_W1, g_bc1, 4 * N1, N1,
                                g_h1[wp], N1, nullptr, 0,
                                row * BM, col * BN, sm);
            }
        } else {                              // layer 2: 4 x 4 tiles
            int t = p - 2;
            if (t >= 0 && t < T_) {
                int b = bid - 116;
                int row = b & 3, col = b >> 2;
                int rp = t & 1, wp = 1 - rp;
                cell_tile<true>(g_h1[wp], N1, N1,
                                g_h2[rp], N2, K2, KP2,
                                g_W2, g_bc2, 4 * N2, N2,
                                g_h2[wp], N2,
                                g_motor + (long)t * OUT_, T_ * OUT_,
                                row * BM, col * BN, sm);
            }
        }
        grid_bar(p + 1);
    }
}

// ---------------- final FC: pred = motor @ Wfc^T + bfc ----------------
__global__ __launch_bounds__(256)
void fc_kernel(float* __restrict__ pred, const float* __restrict__ Wfc,
               const float* __restrict__ bfc)
{
    extern __shared__ float sm[];
    cell_tile<false>(g_motor, OUT_, OUT_,
                     g_motor, OUT_, OUT_, 128,
                     Wfc, bfc, OUT_, 0,
                     pred, OUT_, nullptr, 0,
                     blockIdx.x * BM, 0, sm);
}

// ---------------- launcher ----------------
extern "C" void kernel_launch(void* const* d_in, const int* in_sizes, int n_in,
                              void* d_out, int out_size)
{
    (void)in_sizes; (void)n_in; (void)out_size;
    const float* x    = (const float*)d_in[0];
    const float* h0in = (const float*)d_in[1];
    const float* mask[3]  = { (const float*)d_in[2],  (const float*)d_in[11], (const float*)d_in[20] };
    const float* Wff1[3]  = { (const float*)d_in[3],  (const float*)d_in[12], (const float*)d_in[21] };
    const float* Wff2[3]  = { (const float*)d_in[4],  (const float*)d_in[13], (const float*)d_in[22] };
    const float* Wta[3]   = { (const float*)d_in[5],  (const float*)d_in[14], (const float*)d_in[23] };
    const float* Wtb[3]   = { (const float*)d_in[6],  (const float*)d_in[15], (const float*)d_in[24] };
    const float* bff1[3]  = { (const float*)d_in[7],  (const float*)d_in[16], (const float*)d_in[25] };
    const float* bff2[3]  = { (const float*)d_in[8],  (const float*)d_in[17], (const float*)d_in[26] };
    const float* bta[3]   = { (const float*)d_in[9],  (const float*)d_in[18], (const float*)d_in[27] };
    const float* btb[3]   = { (const float*)d_in[10], (const float*)d_in[19], (const float*)d_in[28] };
    const float* Wfc = (const float*)d_in[29];
    const float* bfc = (const float*)d_in[30];

    float* out  = (float*)d_out;
    float* pred = out;
    float* hn   = out + (long)B_ * T_ * OUT_;

    float* dW[3]; float* dbc[3];
    cudaGetSymbolAddress((void**)&dW[0], g_W0);
    cudaGetSymbolAddress((void**)&dW[1], g_W1);
    cudaGetSymbolAddress((void**)&dW[2], g_W2);
    cudaGetSymbolAddress((void**)&dbc[0], g_bc0);
    cudaGetSymbolAddress((void**)&dbc[1], g_bc1);
    cudaGetSymbolAddress((void**)&dbc[2], g_bc2);

    cudaFuncSetAttribute(rnn_persistent, cudaFuncAttributeMaxDynamicSharedMemorySize, SMEM_BYTES);
    cudaFuncSetAttribute(fc_kernel,      cudaFuncAttributeMaxDynamicSharedMemorySize, SMEM_BYTES);

    const int nL[3] = { N0, N1, N2 };
    const int kL[3] = { K0, K1, K2 };
    const int kP[3] = { KP0, KP1, KP2 };

    for (int l = 0; l < 3; l++) {
        int tot = 4 * nL[l] * kP[l];
        build_w<<<(tot + 255) / 256, 256>>>(Wff1[l], Wff2[l], Wta[l], Wtb[l], mask[l],
                                            bff1[l], bff2[l], bta[l], btb[l],
                                            dW[l], dbc[l], nL[l], kL[l], kP[l]);
    }
    init_h<<<(B_ * UNITS + 255) / 256, 256>>>(h0in);
    reset_bar<<<1, 1>>>();

    rnn_persistent<<<NCTA, 256, SMEM_BYTES>>>(x);

    fc_kernel<<<(B_ * T_) / BM, 256, SMEM_BYTES>>>(pred, Wfc, bfc);
    write_hn<<<(B_ * UNITS + 255) / 256, 256>>>(hn);
}